// round 13
// baseline (speedup 1.0000x reference)
#include <cuda_runtime.h>
#include <cuda_bf16.h>

#define FULLMASK 0xFFFFFFFFu
#define LOG2E 1.4426950408889634f

using u64 = unsigned long long;

__device__ __forceinline__ u64 fma2(u64 a, u64 b, u64 c) {
    u64 d; asm("fma.rn.f32x2 %0,%1,%2,%3;" : "=l"(d) : "l"(a), "l"(b), "l"(c)); return d;
}
__device__ __forceinline__ u64 add2(u64 a, u64 b) {
    u64 d; asm("add.rn.f32x2 %0,%1,%2;" : "=l"(d) : "l"(a), "l"(b)); return d;
}
__device__ __forceinline__ u64 bcast2(float v) {
    u64 d; asm("mov.b64 %0,{%1,%1};" : "=l"(d) : "f"(v)); return d;
}
__device__ __forceinline__ float2 unpk(u64 v) {
    float2 r; asm("mov.b64 {%0,%1},%2;" : "=f"(r.x), "=f"(r.y) : "l"(v)); return r;
}
__device__ __forceinline__ float ex2f(float x) {
    float r; asm("ex2.approx.f32 %0,%1;" : "=f"(r) : "f"(x)); return r;
}
__device__ __forceinline__ float rcpf(float x) {
    float r; asm("rcp.approx.f32 %0,%1;" : "=f"(r) : "f"(x)); return r;
}
__device__ __forceinline__ float rsqf(float x) {
    float r; asm("rsqrt.approx.f32 %0,%1;" : "=f"(r) : "f"(x)); return r;
}

union Row { ulonglong2 u; float4 f; };

// Decomposition: 2 locations per warp, 16 lanes per location.
// u = lane&15, g = lane>>4 (location), h = u>>2 (row group), q = u&3 (d-quad).
// Lane holds rows i = 4h+r (r=0..3), cols d = 4q..4q+3 : P[4] float4 (16 regs).
// Lane owns logits of its 4 rows (one LDG.128, contiguous).
// Reductions: i-sum over h -> xor 4, xor 8 ; d-sum over q -> xor 1, xor 2.
// All reductions stay inside the 16-lane group (g never crossed).
//
// Small register footprint (~50) -> 36-40 resident warps/SM, so the bursty
// LDG phase of many warps overlaps the compute of others.
//
// b kept in log2-space; softmax 1/s never materialized (cancels in squash):
//   out = a * sq * rcp(s^2+sq) * rsq(sq + eps*s^2).   No max-subtract.
__global__ void __launch_bounds__(128) routing_kernel(
    const float* __restrict__ pred,
    const float* __restrict__ b_in,
    const int*   __restrict__ nit,
    float*       __restrict__ out,
    int n_loc, int ohw, int ohw_mask)
{
    const int lane = threadIdx.x & 31;
    const int u = lane & 15;
    const int g = lane >> 4;
    const int h = u >> 2;
    const int q = u & 3;
    const unsigned w = blockIdx.x * (blockDim.x >> 5) + (threadIdx.x >> 5);
    if (w * 2u >= (unsigned)n_loc) return;      // warp-uniform guard
    const unsigned loc = w * 2u + g;

    // ---- pred tile: 4 coalesced LDG.128 rounds (2 KB per location) ----
    const float4* p4 = reinterpret_cast<const float4*>(pred);
    const int pbase = (int)(w * 128u) + 64 * g + 16 * h + q;
    Row P[4];
#pragma unroll
    for (int r = 0; r < 4; ++r)
        P[r].f = p4[pbase + 4 * r];

    // ---- owned rows' logits: one LDG.128 (log2-space) ----
    const unsigned bloc = ohw_mask ? (loc & (unsigned)ohw_mask)
                                   : (loc % (unsigned)ohw);
    float bb[4];
    {
        const float4 bv = *reinterpret_cast<const float4*>(
            b_in + (size_t)bloc * 16 + 4 * h);
        bb[0] = bv.x * LOG2E; bb[1] = bv.y * LOG2E;
        bb[2] = bv.z * LOG2E; bb[3] = bv.w * LOG2E;
    }

    const int iters = *nit;
    float o0, o1, o2, o3;

    auto pass = [&]() {
        const float e0 = ex2f(bb[0]), e1 = ex2f(bb[1]);
        const float e2 = ex2f(bb[2]), e3 = ex2f(bb[3]);

        // sum of exps over all 16 i: local 4 + butterfly over h (xor4, xor8)
        float s = (e0 + e1) + (e2 + e3);
        s += __shfl_xor_sync(FULLMASK, s, 4);
        s += __shfl_xor_sync(FULLMASK, s, 8);

        // unnormalized weighted sum over local 4 rows (packed f32x2)
        u64 a01, a23;
        {
            const u64 v0 = bcast2(e0), v1 = bcast2(e1);
            const u64 v2 = bcast2(e2), v3 = bcast2(e3);
            u64 x01 = fma2(v1, P[1].u.x, fma2(v0, P[0].u.x, 0ull));
            u64 y01 = fma2(v3, P[3].u.x, fma2(v2, P[2].u.x, 0ull));
            u64 x23 = fma2(v1, P[1].u.y, fma2(v0, P[0].u.y, 0ull));
            u64 y23 = fma2(v3, P[3].u.y, fma2(v2, P[2].u.y, 0ull));
            a01 = add2(x01, y01);
            a23 = add2(x23, y23);
        }
        // i-reduce over h: xor 4, xor 8
        a01 = add2(a01, __shfl_xor_sync(FULLMASK, a01, 4));
        a23 = add2(a23, __shfl_xor_sync(FULLMASK, a23, 4));
        a01 = add2(a01, __shfl_xor_sync(FULLMASK, a01, 8));
        a23 = add2(a23, __shfl_xor_sync(FULLMASK, a23, 8));

        const float2 lo = unpk(a01), hi = unpk(a23);
        const float a0 = lo.x, a1 = lo.y, a2 = hi.x, a3 = hi.y;

        // |a|^2 over 16 d: local quad + d-reduce over q (xor1, xor2)
        float sq = fmaf(a3, a3, fmaf(a2, a2, fmaf(a1, a1, a0 * a0)));
        sq += __shfl_xor_sync(FULLMASK, sq, 1);
        sq += __shfl_xor_sync(FULLMASK, sq, 2);

        // folded squash: 2 MUFU, softmax 1/s fully cancelled
        const float s2 = s * s;
        const float f  = sq * rcpf(s2 + sq) * rsqf(fmaf(1e-7f, s2, sq));
        o0 = a0 * f; o1 = a1 * f; o2 = a2 * f; o3 = a3 * f;
    };

    pass();
    for (int it = 0; it < iters; ++it) {
#pragma unroll
        for (int r = 0; r < 4; ++r) {
            // partial dot over my 4 cols, then d-reduce over q
            float p = fmaf(P[r].f.w, o3,
                      fmaf(P[r].f.z, o2,
                      fmaf(P[r].f.y, o1, P[r].f.x * o0)));
            p += __shfl_xor_sync(FULLMASK, p, 1);
            p += __shfl_xor_sync(FULLMASK, p, 2);
            bb[r] = fmaf(p, LOG2E, bb[r]);      // log2-space update
        }
        pass();
    }

    // h==0 lanes of each location hold quads q=0..3
    if (h == 0)
        reinterpret_cast<float4*>(out)[(size_t)loc * 4 + q] =
            make_float4(o0, o1, o2, o3);
}

extern "C" void kernel_launch(void* const* d_in, const int* in_sizes, int n_in,
                              void* d_out, int out_size) {
    const float* pred = (const float*)d_in[0];
    const float* b    = (const float*)d_in[1];
    const int*   nit  = (const int*)d_in[2];
    float* out = (float*)d_out;

    const int n_loc = in_sizes[0] / 256;   // B*O*H*W
    const int ohw   = in_sizes[1] / 16;    // O*H*W
    const int ohw_mask = ((ohw & (ohw - 1)) == 0) ? (ohw - 1) : 0;

    const int warps  = (n_loc + 1) / 2;    // 2 locations per warp
    const int blocks = (warps + 3) / 4;    // 4 warps per block (128 threads)
    routing_kernel<<<blocks, 128>>>(pred, b, nit, out, n_loc, ohw, ohw_mask);
}

// round 14
// speedup vs baseline: 1.3351x; 1.3351x over previous
#include <cuda_runtime.h>
#include <cuda_bf16.h>

#define FULLMASK 0xFFFFFFFFu
#define LOG2E 1.4426950408889634f

using u64 = unsigned long long;

__device__ __forceinline__ u64 fma2(u64 a, u64 b, u64 c) {
    u64 d; asm("fma.rn.f32x2 %0,%1,%2,%3;" : "=l"(d) : "l"(a), "l"(b), "l"(c)); return d;
}
__device__ __forceinline__ u64 add2(u64 a, u64 b) {
    u64 d; asm("add.rn.f32x2 %0,%1,%2;" : "=l"(d) : "l"(a), "l"(b)); return d;
}
__device__ __forceinline__ u64 bcast2(float v) {
    u64 d; asm("mov.b64 %0,{%1,%1};" : "=l"(d) : "f"(v)); return d;
}
__device__ __forceinline__ float2 unpk(u64 v) {
    float2 r; asm("mov.b64 {%0,%1},%2;" : "=f"(r.x), "=f"(r.y) : "l"(v)); return r;
}
__device__ __forceinline__ float ex2f(float x) {
    float r; asm("ex2.approx.f32 %0,%1;" : "=f"(r) : "f"(x)); return r;
}
__device__ __forceinline__ float rcpf(float x) {
    float r; asm("rcp.approx.f32 %0,%1;" : "=f"(r) : "f"(x)); return r;
}
__device__ __forceinline__ float rsqf(float x) {
    float r; asm("rsqrt.approx.f32 %0,%1;" : "=f"(r) : "f"(x)); return r;
}

union Row { ulonglong2 u; float4 f; };

// Layout: 4 locations per warp, 8 lanes per location.
// t=lane&7, h=t>>2 (row-half), q=t&3 (d-quad). Lane holds the 8 rows of its
// half in XOR ORDER: slot (k,j), k=0..3, j=0..1 -> row i = 8h + 2*(q^k) + j,
// columns d = 4q..4q+3. Lane OWNS rows 8h+2q, 8h+2q+1 (logits bb0/bb1 and
// their exponentials). Because xor is involutive, both directions of quad
// communication are plain shfl.xor (width 4, compile-time slots):
//   e-gather:      e[2k+j] = shfl_xor(e_j, k)
//   agree reduce:  p_j     = pp[j] + sum_k shfl_xor(pp[2k+j], k)
// (lane q receives from q^k its slot 2k+j = partial of row 2((q^k)^k)=2q ✓)
//
// b kept in log2-space; softmax 1/s never materialized (cancels in squash):
//   out = a * sq * rcp(s^2+sq) * rsq(sq + eps*s^2).   No max-subtract.
//
// 128-thread blocks + 9 blocks/SM (reg cap 56) -> 36 resident warps (56% occ)
// so the issue ceiling (~80%) is reachable with the cheapest known body.
__global__ void __launch_bounds__(128, 9) routing_kernel(
    const float* __restrict__ pred,
    const float* __restrict__ b_in,
    const int*   __restrict__ nit,
    float*       __restrict__ out,
    int n_loc, int ohw, int ohw_mask)
{
    const int lane = threadIdx.x & 31;
    const int t = lane & 7;
    const int h = t >> 2;
    const int q = t & 3;
    const int g = lane >> 3;
    const unsigned w = blockIdx.x * (blockDim.x >> 5) + (threadIdx.x >> 5);
    if (w * 4u >= (unsigned)n_loc) return;      // warp-uniform guard
    const unsigned loc = w * 4u + g;

    // ---- pred tile: 8 coalesced LDG.128, XOR-ordered rows ----
    const ulonglong2* pp =
        reinterpret_cast<const ulonglong2*>(pred) + (size_t)w * 256;
    Row P[8];
    {
        const int base = 64 * g + 32 * h + q;
#pragma unroll
        for (int k = 0; k < 4; ++k) {
            const int off = 8 * (q ^ k);
            P[2 * k].u     = pp[base + off];
            P[2 * k + 1].u = pp[base + off + 4];
        }
    }

    // ---- owned rows' logits: one LDG.64 (log2-space) ----
    const unsigned bloc = ohw_mask ? (loc & (unsigned)ohw_mask)
                                   : (loc % (unsigned)ohw);
    float bb0, bb1;
    {
        const float2 b2 = *reinterpret_cast<const float2*>(
            b_in + (size_t)bloc * 16 + 8 * h + 2 * q);
        bb0 = b2.x * LOG2E;
        bb1 = b2.y * LOG2E;
    }

    const int iters = *nit;
    float o0, o1, o2, o3;

    auto pass = [&]() {
        const float e0 = ex2f(bb0), e1 = ex2f(bb1);

        // k=0: own rows (chain X)
        u64 x01 = fma2(bcast2(e0), P[0].u.x, 0ull);
        u64 x23 = fma2(bcast2(e0), P[0].u.y, 0ull);
        x01 = fma2(bcast2(e1), P[1].u.x, x01);
        x23 = fma2(bcast2(e1), P[1].u.y, x23);
        float s01 = e0 + e1;

        // k=1 (chain Y)
        float ea = __shfl_xor_sync(FULLMASK, e0, 1, 4);
        float eb = __shfl_xor_sync(FULLMASK, e1, 1, 4);
        u64 y01 = fma2(bcast2(ea), P[2].u.x, 0ull);
        u64 y23 = fma2(bcast2(ea), P[2].u.y, 0ull);
        y01 = fma2(bcast2(eb), P[3].u.x, y01);
        y23 = fma2(bcast2(eb), P[3].u.y, y23);
        float s23 = ea + eb;

        // k=2 (chain X)
        ea = __shfl_xor_sync(FULLMASK, e0, 2, 4);
        eb = __shfl_xor_sync(FULLMASK, e1, 2, 4);
        x01 = fma2(bcast2(ea), P[4].u.x, x01);
        x23 = fma2(bcast2(ea), P[4].u.y, x23);
        x01 = fma2(bcast2(eb), P[5].u.x, x01);
        x23 = fma2(bcast2(eb), P[5].u.y, x23);
        s01 += ea + eb;

        // k=3 (chain Y)
        ea = __shfl_xor_sync(FULLMASK, e0, 3, 4);
        eb = __shfl_xor_sync(FULLMASK, e1, 3, 4);
        y01 = fma2(bcast2(ea), P[6].u.x, y01);
        y23 = fma2(bcast2(ea), P[6].u.y, y23);
        y01 = fma2(bcast2(eb), P[7].u.x, y01);
        y23 = fma2(bcast2(eb), P[7].u.y, y23);
        s23 += ea + eb;

        // combine chains, then the other row-half (xor 4, full width)
        u64 a01 = add2(x01, y01);
        u64 a23 = add2(x23, y23);
        float s = s01 + s23;
        s += __shfl_xor_sync(FULLMASK, s, 4);
        a01 = add2(a01, __shfl_xor_sync(FULLMASK, a01, 4));
        a23 = add2(a23, __shfl_xor_sync(FULLMASK, a23, 4));

        const float2 lo = unpk(a01), hi = unpk(a23);
        const float a0 = lo.x, a1 = lo.y, a2 = hi.x, a3 = hi.y;

        // |a|^2 over 16 d: local quad + d-reduce over q
        float sq = fmaf(a3, a3, fmaf(a2, a2, fmaf(a1, a1, a0 * a0)));
        sq += __shfl_xor_sync(FULLMASK, sq, 1);
        sq += __shfl_xor_sync(FULLMASK, sq, 2);

        // folded squash: 2 MUFU, softmax 1/s fully cancelled
        const float s2 = s * s;
        const float f  = sq * rcpf(s2 + sq) * rsqf(fmaf(1e-7f, s2, sq));
        o0 = a0 * f; o1 = a1 * f; o2 = a2 * f; o3 = a3 * f;
    };

    pass();
    for (int it = 0; it < iters; ++it) {
        float pd[8];
#pragma unroll
        for (int m = 0; m < 8; ++m)
            pd[m] = fmaf(P[m].f.w, o3,
                    fmaf(P[m].f.z, o2,
                    fmaf(P[m].f.y, o1, P[m].f.x * o0)));
        // xor ring-reduce (width 4): slot 2k+j from partner q^k is my row j
        const float r10 = __shfl_xor_sync(FULLMASK, pd[2], 1, 4);
        const float r11 = __shfl_xor_sync(FULLMASK, pd[3], 1, 4);
        const float r20 = __shfl_xor_sync(FULLMASK, pd[4], 2, 4);
        const float r21 = __shfl_xor_sync(FULLMASK, pd[5], 2, 4);
        const float r30 = __shfl_xor_sync(FULLMASK, pd[6], 3, 4);
        const float r31 = __shfl_xor_sync(FULLMASK, pd[7], 3, 4);
        const float p0 = (pd[0] + r10) + (r20 + r30);
        const float p1 = (pd[1] + r11) + (r21 + r31);

        bb0 = fmaf(p0, LOG2E, bb0);
        bb1 = fmaf(p1, LOG2E, bb1);
        pass();
    }

    if (h == 0)
        reinterpret_cast<float4*>(out)[(size_t)loc * 4 + q] =
            make_float4(o0, o1, o2, o3);
}

extern "C" void kernel_launch(void* const* d_in, const int* in_sizes, int n_in,
                              void* d_out, int out_size) {
    const float* pred = (const float*)d_in[0];
    const float* b    = (const float*)d_in[1];
    const int*   nit  = (const int*)d_in[2];
    float* out = (float*)d_out;

    const int n_loc = in_sizes[0] / 256;   // B*O*H*W
    const int ohw   = in_sizes[1] / 16;    // O*H*W
    const int ohw_mask = ((ohw & (ohw - 1)) == 0) ? (ohw - 1) : 0;

    const int warps  = (n_loc + 3) / 4;    // 4 locations per warp
    const int blocks = (warps + 3) / 4;    // 4 warps per block (128 threads)
    routing_kernel<<<blocks, 128>>>(pred, b, nit, out, n_loc, ohw, ohw_mask);
}